// round 9
// baseline (speedup 1.0000x reference)
#include <cuda_runtime.h>
#include <cuda_fp16.h>
#include <cstdint>
#include <math.h>

#define B_      64
#define L_      2048
#define DTS     8
#define DSEQ    120
#define DIN     128
#define H_      64
#define NSPLIT  16
#define TILE_M  128
#define TPB     256
#define SLOPE   0.2291666666666667f

// smem layout (bytes): header 5KB, X (32KB), W (32KB) => 69.5KB, 3 blocks/SM
#define HDR     5120
#define XH_OFF  5120
#define WH_OFF  37888
#define SMEM_TOTAL 70656

__device__ float g_m[B_ * NSPLIT];
__device__ float g_s[B_ * NSPLIT];
__device__ float g_acc[B_ * NSPLIT * H_];
__device__ int   g_cnt[B_];      // zero-init; self-resetting per replay

__device__ __forceinline__ uint32_t smem_u32(const void* p) {
    uint32_t a;
    asm("{ .reg .u64 t; cvta.to.shared.u64 t, %1; cvt.u32.u64 %0, t; }" : "=r"(a) : "l"(p));
    return a;
}
__device__ __forceinline__ float rrelu(float x) { return x >= 0.f ? x : x * SLOPE; }
__device__ __forceinline__ uint32_t cvt_h2(float f0, float f1) {
    __half2 hh = __floats2half2_rn(f0, f1);
    return *reinterpret_cast<uint32_t*>(&hh);
}

#define LDSM_X4(r0, r1, r2, r3, addr) \
    asm volatile("ldmatrix.sync.aligned.m8n8.x4.shared.b16 {%0,%1,%2,%3}, [%4];" \
        : "=r"(r0), "=r"(r1), "=r"(r2), "=r"(r3) : "r"(addr))
#define LDSM_X4_T(r0, r1, r2, r3, addr) \
    asm volatile("ldmatrix.sync.aligned.m8n8.x4.trans.shared.b16 {%0,%1,%2,%3}, [%4];" \
        : "=r"(r0), "=r"(r1), "=r"(r2), "=r"(r3) : "r"(addr))

__device__ __forceinline__ void mma_f16(float (&c)[4], uint32_t a0, uint32_t a1,
                                        uint32_t a2, uint32_t a3,
                                        uint32_t b0, uint32_t b1) {
    asm volatile(
        "mma.sync.aligned.m16n8k16.row.col.f32.f16.f16.f32 "
        "{%0,%1,%2,%3}, {%4,%5,%6,%7}, {%8,%9}, {%0,%1,%2,%3};"
        : "+f"(c[0]), "+f"(c[1]), "+f"(c[2]), "+f"(c[3])
        : "r"(a0), "r"(a1), "r"(a2), "r"(a3), "r"(b0), "r"(b1));
}

// one GEMM pass: this warp's 32 rows (a_row0/a_row1) x 32-col strip (chunk_base)
__device__ __forceinline__ void gemm_pass(uint32_t a_row0, uint32_t a_row1,
                                          uint32_t w_base, uint32_t chunk_base,
                                          int ci, int rm, int roff,
                                          float (&acc)[2][4][4]) {
#pragma unroll
    for (int ms = 0; ms < 2; ++ms)
#pragma unroll
        for (int n = 0; n < 4; ++n)
#pragma unroll
            for (int i = 0; i < 4; ++i) acc[ms][n][i] = 0.f;
#pragma unroll
    for (int ks = 0; ks < 8; ++ks) {
        uint32_t aoff = ((uint32_t)((2 * ks + ci) ^ rm)) << 4;
        uint32_t a00, a01, a02, a03, a10, a11, a12, a13;
        LDSM_X4(a00, a01, a02, a03, a_row0 + aoff);
        LDSM_X4(a10, a11, a12, a13, a_row1 + aoff);
        uint32_t wh_row = w_base + (uint32_t)((ks * 16 + roff) * 256);
#pragma unroll
        for (int ntp = 0; ntp < 2; ++ntp) {
            uint32_t boff = ((uint32_t)((chunk_base + 2 * ntp + ci) ^ rm)) << 4;
            uint32_t b0, b1, b2, b3;
            LDSM_X4_T(b0, b1, b2, b3, wh_row + boff);
            mma_f16(acc[0][2 * ntp],     a00, a01, a02, a03, b0, b1);
            mma_f16(acc[0][2 * ntp + 1], a00, a01, a02, a03, b2, b3);
            mma_f16(acc[1][2 * ntp],     a10, a11, a12, a13, b0, b1);
            mma_f16(acc[1][2 * ntp + 1], a10, a11, a12, a13, b2, b3);
        }
    }
}

// ---------------------------------------------------------------------------
// fused: per (split, batch) block — one 128-token tile.
// All 8 warps: K-GEMM (32r x 32c strip) -> scores -> softmax -> V-GEMM (same
// regs) -> weighted V. rw = wid&3 (row group), cw = wid>>2 (col strip).
// ---------------------------------------------------------------------------
__global__ void __launch_bounds__(TPB, 3)
fused_attn(const float* __restrict__ ts, const float* __restrict__ seq,
           const int* __restrict__ lengths,
           const float* __restrict__ Wk, const float* __restrict__ bk,
           const float* __restrict__ Wq, const float* __restrict__ bq,
           const float* __restrict__ Wv, const float* __restrict__ bv,
           float* __restrict__ out) {
    int b   = blockIdx.y;
    int sp  = blockIdx.x;
    int len = lengths[b];
    int start = sp * TILE_M;
    int tid = threadIdx.x;
    int wid = tid >> 5, lane = tid & 31;
    int idx = b * NSPLIT + sp;
    int nlive = min(NSPLIT, (len + TILE_M - 1) >> 7);

    if (sp >= nlive) return;   // dead split

    extern __shared__ char smem[];
    uint32_t sb = smem_u32(smem);
    float* sQ      = (float*)smem;             // 64
    float* sQpart  = (float*)(smem + 256);     // 256
    float* sBias   = (float*)(smem + 1280);    // 128
    float* sXlast  = (float*)(smem + 1792);    // 128
    float* sScoreP = (float*)(smem + 2304);    // 2 x 128 (strip partials)
    float* sScore  = (float*)(smem + 3328);    // 128 (combined)
    float* sRedV   = (float*)(smem + 3840);    // 4 x 64
    float* sM      = (float*)(smem + 4864);
    float* sSum    = (float*)(smem + 4868);
    int*   sLast   = (int*)(smem + 4872);

    // ---- bias + last-token row ----
    if (tid < DIN) {
        sBias[tid] = (tid < H_) ? bk[tid] : bv[tid - H_];
        int l = len - 1;
        sXlast[tid] = (tid < DTS) ? ts[((size_t)b * L_ + l) * DTS + tid]
                                  : seq[((size_t)b * L_ + l) * DSEQ + (tid - DTS)];
    }

    // ---- W tile: [Wk | Wv] fp32 -> fp16, swizzled ----
#pragma unroll
    for (int it = 0; it < 8; ++it) {
        int j = tid + it * TPB;
        int k = j >> 4, ch = j & 15;
        int n0 = ch * 8;
        const float* src = (n0 < H_) ? (Wk + k * H_ + n0) : (Wv + k * H_ + n0 - H_);
        float4 f0 = ((const float4*)src)[0];
        float4 f1 = ((const float4*)src)[1];
        uint4 v = make_uint4(cvt_h2(f0.x, f0.y), cvt_h2(f0.z, f0.w),
                             cvt_h2(f1.x, f1.y), cvt_h2(f1.z, f1.w));
        uint32_t off = (uint32_t)(k * 256 + ((ch ^ (k & 7)) << 4));
        *(uint4*)(smem + WH_OFF + off) = v;
    }

    // ---- X tile: fp32 -> fp16, swizzled ----
#pragma unroll
    for (int it = 0; it < 8; ++it) {
        int j = tid + it * TPB;
        int row = j >> 4, ch = j & 15;
        int token = start + row;
        const float* src = (ch == 0)
            ? (ts + ((size_t)b * L_ + token) * DTS)
            : (seq + ((size_t)b * L_ + token) * DSEQ + (ch * 8 - 8));
        float4 f0 = ((const float4*)src)[0];
        float4 f1 = ((const float4*)src)[1];
        uint4 v = make_uint4(cvt_h2(f0.x, f0.y), cvt_h2(f0.z, f0.w),
                             cvt_h2(f1.x, f1.y), cvt_h2(f1.z, f1.w));
        uint32_t off = (uint32_t)(row * 256 + ((ch ^ (row & 7)) << 4));
        *(uint4*)(smem + XH_OFF + off) = v;
    }
    __syncthreads();

    // ---- q partials (coalesced, 4 parts x 64 h) + finalize ----
    {
        int h = tid & 63, part = tid >> 6;
        float s = 0.f;
        const float* wq = Wq + part * 32 * H_ + h;
#pragma unroll 8
        for (int d = 0; d < 32; ++d) s += sXlast[part * 32 + d] * wq[d * H_];
        sQpart[part * 64 + h] = s;
    }
    __syncthreads();
    if (tid < H_) {
        float s = sQpart[tid] + sQpart[64 + tid] + sQpart[128 + tid] + sQpart[192 + tid];
        sQ[tid] = rrelu(s + bq[tid]);
    }
    __syncthreads();

    int rw = wid & 3;                 // row group (32 rows)
    int cw = wid >> 2;                // col strip (32 cols)
    int li = lane >> 3, lr = lane & 7;
    int roff = ((li & 1) << 3) + lr;
    int ci   = li >> 1;
    int rm   = roff & 7;
    int g = lane >> 2, t = lane & 3;

    uint32_t a_row0 = sb + XH_OFF + (uint32_t)((rw * 32 + roff) * 256);
    uint32_t a_row1 = a_row0 + 16 * 256;
    uint32_t w_base = sb + WH_OFF;

    float acc[2][4][4];

    // =================== K pass ===================
    gemm_pass(a_row0, a_row1, w_base, (uint32_t)(cw * 4), ci, rm, roff, acc);

    // partial scores over this warp's 32 cols
#pragma unroll
    for (int ms = 0; ms < 2; ++ms) {
        float s0 = 0.f, s1 = 0.f;
#pragma unroll
        for (int nt = 0; nt < 4; ++nt) {
            int c0 = cw * 32 + 8 * nt + 2 * t, c1 = c0 + 1;
            float q0 = sQ[c0], q1 = sQ[c1];
            float b0 = sBias[c0], b1 = sBias[c1];
            s0 += q0 * rrelu(acc[ms][nt][0] + b0) + q1 * rrelu(acc[ms][nt][1] + b1);
            s1 += q0 * rrelu(acc[ms][nt][2] + b0) + q1 * rrelu(acc[ms][nt][3] + b1);
        }
        s0 += __shfl_xor_sync(0xffffffffu, s0, 1);
        s0 += __shfl_xor_sync(0xffffffffu, s0, 2);
        s1 += __shfl_xor_sync(0xffffffffu, s1, 1);
        s1 += __shfl_xor_sync(0xffffffffu, s1, 2);
        if (t == 0) {
            int r0 = rw * 32 + ms * 16 + g;
            sScoreP[cw * 128 + r0] = s0;
            sScoreP[cw * 128 + r0 + 8] = s1;
        }
    }
    __syncthreads();

    // ---- combine strips + softmax (warp 0) ----
    if (wid == 0) {
        float v[4];
#pragma unroll
        for (int i = 0; i < 4; ++i) {
            int r = lane + 32 * i;
            float x = sScoreP[r] + sScoreP[128 + r];
            if (start + r >= len) x = -INFINITY;
            sScore[r] = x;
            v[i] = x;
        }
        float mx = fmaxf(fmaxf(v[0], v[1]), fmaxf(v[2], v[3]));
#pragma unroll
        for (int o = 16; o >= 1; o >>= 1)
            mx = fmaxf(mx, __shfl_xor_sync(0xffffffffu, mx, o));
        float sum = __expf(v[0] - mx) + __expf(v[1] - mx)
                  + __expf(v[2] - mx) + __expf(v[3] - mx);
#pragma unroll
        for (int o = 16; o >= 1; o >>= 1)
            sum += __shfl_xor_sync(0xffffffffu, sum, o);
        if (lane == 0) { *sM = mx; *sSum = sum; }
    }
    __syncthreads();

    // =================== V pass (same registers) ===================
    gemm_pass(a_row0, a_row1, w_base, (uint32_t)(8 + cw * 4), ci, rm, roff, acc);

    {
        float mx = *sM;
        int rbase = rw * 32;
        float wa = __expf(sScore[rbase + g]      - mx);
        float wb = __expf(sScore[rbase + g + 8]  - mx);
        float wc = __expf(sScore[rbase + g + 16] - mx);
        float wd = __expf(sScore[rbase + g + 24] - mx);
#pragma unroll
        for (int nt = 0; nt < 4; ++nt) {
            int lc = cw * 32 + 8 * nt + 2 * t;       // V-local col 0..63
            float b0 = sBias[64 + lc], b1 = sBias[64 + lc + 1];
            float p0 = wa * rrelu(acc[0][nt][0] + b0) + wb * rrelu(acc[0][nt][2] + b0)
                     + wc * rrelu(acc[1][nt][0] + b0) + wd * rrelu(acc[1][nt][2] + b0);
            float p1 = wa * rrelu(acc[0][nt][1] + b1) + wb * rrelu(acc[0][nt][3] + b1)
                     + wc * rrelu(acc[1][nt][1] + b1) + wd * rrelu(acc[1][nt][3] + b1);
            p0 += __shfl_xor_sync(0xffffffffu, p0, 4);
            p0 += __shfl_xor_sync(0xffffffffu, p0, 8);
            p0 += __shfl_xor_sync(0xffffffffu, p0, 16);
            p1 += __shfl_xor_sync(0xffffffffu, p1, 4);
            p1 += __shfl_xor_sync(0xffffffffu, p1, 8);
            p1 += __shfl_xor_sync(0xffffffffu, p1, 16);
            if (g == 0) {
                sRedV[rw * 64 + lc] = p0;
                sRedV[rw * 64 + lc + 1] = p1;
            }
        }
    }
    __syncthreads();

    // ---- per-split partials ----
    if (tid < H_) {
        g_acc[idx * H_ + tid] = sRedV[tid] + sRedV[64 + tid]
                              + sRedV[128 + tid] + sRedV[192 + tid];
    }
    if (tid == 0) { g_m[idx] = *sM; g_s[idx] = *sSum; }

    // ---- last-block combine (threadfence reduction) ----
    __threadfence();
    __syncthreads();
    if (tid == 0) {
        int old = atomicAdd(&g_cnt[b], 1);
        *sLast = (old == nlive - 1);
    }
    __syncthreads();
    if (*sLast) {
        if (tid < H_) {
            volatile float* vm = g_m + b * NSPLIT;
            volatile float* vs = g_s + b * NSPLIT;
            volatile float* va = g_acc + (size_t)b * NSPLIT * H_;
            float MM = -INFINITY;
            for (int i = 0; i < nlive; ++i) MM = fmaxf(MM, vm[i]);
            float S = 0.f, A = 0.f;
            for (int i = 0; i < nlive; ++i) {
                float e = __expf(vm[i] - MM);
                S += vs[i] * e;
                A += va[i * H_ + tid] * e;
            }
            out[b * H_ + tid] = A / S;
        }
        if (tid == 0) g_cnt[b] = 0;   // reset for next replay
    }
}

// ---------------------------------------------------------------------------
extern "C" void kernel_launch(void* const* d_in, const int* in_sizes, int n_in,
                              void* d_out, int out_size) {
    const float* ts      = (const float*)d_in[0];
    const float* seq     = (const float*)d_in[1];
    const int*   lengths = (const int*)  d_in[2];
    const float* Wk      = (const float*)d_in[3];
    const float* bk      = (const float*)d_in[4];
    const float* Wq      = (const float*)d_in[5];
    const float* bq      = (const float*)d_in[6];
    const float* Wv      = (const float*)d_in[7];
    const float* bv      = (const float*)d_in[8];
    float* out = (float*)d_out;

    static int configured = 0;
    if (!configured) {
        cudaFuncSetAttribute(fused_attn,
                             cudaFuncAttributeMaxDynamicSharedMemorySize, SMEM_TOTAL);
        configured = 1;
    }

    dim3 grid(NSPLIT, B_);
    fused_attn<<<grid, TPB, SMEM_TOTAL>>>(ts, seq, lengths, Wk, bk, Wq, bq, Wv, bv, out);
}

// round 10
// speedup vs baseline: 1.0022x; 1.0022x over previous
#include <cuda_runtime.h>
#include <cuda_fp16.h>
#include <cstdint>
#include <math.h>

#define B_      64
#define L_      2048
#define DTS     8
#define DSEQ    120
#define DIN     128
#define H_      64
#define NSPLIT  8
#define TILE_B  256              // tokens per block
#define TILE_M  128              // tokens per MMA tile
#define TPB     256
#define SLOPE   0.2291666666666667f

// smem layout (bytes): header 5KB + W (32KB)
#define HDR     5120
#define WH_OFF  5120
#define SMEM_TOTAL 37888

__device__ float g_m[B_ * NSPLIT];
__device__ float g_s[B_ * NSPLIT];
__device__ float g_acc[B_ * NSPLIT * H_];
__device__ int   g_cnt[B_];      // zero-init; self-resetting per replay

__device__ __forceinline__ uint32_t smem_u32(const void* p) {
    uint32_t a;
    asm("{ .reg .u64 t; cvta.to.shared.u64 t, %1; cvt.u32.u64 %0, t; }" : "=r"(a) : "l"(p));
    return a;
}
__device__ __forceinline__ float rrelu(float x) { return x >= 0.f ? x : x * SLOPE; }
__device__ __forceinline__ uint32_t cvt_h2(float f0, float f1) {
    __half2 hh = __floats2half2_rn(f0, f1);
    return *reinterpret_cast<uint32_t*>(&hh);
}
__device__ __forceinline__ uint32_t pack2(const float* p) {
    float2 v = *(const float2*)p;
    return cvt_h2(v.x, v.y);
}

#define LDSM_X4_T(r0, r1, r2, r3, addr) \
    asm volatile("ldmatrix.sync.aligned.m8n8.x4.trans.shared.b16 {%0,%1,%2,%3}, [%4];" \
        : "=r"(r0), "=r"(r1), "=r"(r2), "=r"(r3) : "r"(addr))

__device__ __forceinline__ void mma_f16(float (&c)[4], uint32_t a0, uint32_t a1,
                                        uint32_t a2, uint32_t a3,
                                        uint32_t b0, uint32_t b1) {
    asm volatile(
        "mma.sync.aligned.m16n8k16.row.col.f32.f16.f16.f32 "
        "{%0,%1,%2,%3}, {%4,%5,%6,%7}, {%8,%9}, {%0,%1,%2,%3};"
        : "+f"(c[0]), "+f"(c[1]), "+f"(c[2]), "+f"(c[3])
        : "r"(a0), "r"(a1), "r"(a2), "r"(a3), "r"(b0), "r"(b1));
}

// ---------------------------------------------------------------------------
// fused: per (split, batch) block — 256-token span, two 128-row MMA tiles.
// A-fragments loaded DIRECTLY from global (fp32 pairs -> f16x2), no X smem.
// Warps 0-3: K cols 0-63; warps 4-7: V cols 64-127; each warp 32 rows.
// ---------------------------------------------------------------------------
__global__ void __launch_bounds__(TPB, 2)
fused_attn(const float* __restrict__ ts, const float* __restrict__ seq,
           const int* __restrict__ lengths,
           const float* __restrict__ Wk, const float* __restrict__ bk,
           const float* __restrict__ Wq, const float* __restrict__ bq,
           const float* __restrict__ Wv, const float* __restrict__ bv,
           float* __restrict__ out) {
    int b   = blockIdx.y;
    int sp  = blockIdx.x;
    int len = lengths[b];
    int start = sp * TILE_B;
    int tid = threadIdx.x;
    int wid = tid >> 5, lane = tid & 31;
    int idx = b * NSPLIT + sp;
    int nlive = min(NSPLIT, (len + TILE_B - 1) / TILE_B);

    if (sp >= nlive) return;   // dead split
    int ntiles = min(2, (len - start + TILE_M - 1) >> 7);

    extern __shared__ char smem[];
    uint32_t sb = smem_u32(smem);
    float* sQ      = (float*)smem;             // 64
    float* sQpart  = (float*)(smem + 256);     // 256
    float* sBias   = (float*)(smem + 1280);    // 128
    float* sScore  = (float*)(smem + 1792);    // 128
    float* sRed0   = (float*)(smem + 2304);    // 256
    float* sRed1   = (float*)(smem + 3328);    // 256
    int*   sLast   = (int*)(smem + 4352);

    // ---- bias ----
    if (tid < DIN) sBias[tid] = (tid < H_) ? bk[tid] : bv[tid - H_];

    // ---- W tile: [Wk | Wv] fp32 -> fp16, swizzled ----
#pragma unroll
    for (int it = 0; it < 8; ++it) {
        int j = tid + it * TPB;
        int k = j >> 4, ch = j & 15;
        int n0 = ch * 8;
        const float* src = (n0 < H_) ? (Wk + k * H_ + n0) : (Wv + k * H_ + n0 - H_);
        float4 f0 = ((const float4*)src)[0];
        float4 f1 = ((const float4*)src)[1];
        uint4 v = make_uint4(cvt_h2(f0.x, f0.y), cvt_h2(f0.z, f0.w),
                             cvt_h2(f1.x, f1.y), cvt_h2(f1.z, f1.w));
        uint32_t off = (uint32_t)(k * 256 + ((ch ^ (k & 7)) << 4));
        *(uint4*)(smem + WH_OFF + off) = v;
    }

    // ---- q partials: direct global reads (x_last uniform, Wq coalesced) ----
    {
        int h = tid & 63, part = tid >> 6;
        const float* wq = Wq + part * 32 * H_ + h;
        const float* tl_ = ts + ((size_t)b * L_ + (len - 1)) * DTS;
        const float* sl_ = seq + ((size_t)b * L_ + (len - 1)) * DSEQ;
        float s = 0.f;
#pragma unroll 8
        for (int d = 0; d < 32; ++d) {
            int dd = part * 32 + d;
            float xv = (dd < DTS) ? tl_[dd] : sl_[dd - DTS];
            s += xv * wq[d * H_];
        }
        sQpart[part * 64 + h] = s;
    }
    __syncthreads();
    if (tid < H_) {
        float s = sQpart[tid] + sQpart[64 + tid] + sQpart[128 + tid] + sQpart[192 + tid];
        sQ[tid] = rrelu(s + bq[tid]);
    }
    __syncthreads();

    int kw = wid & 3;                 // row group
    int isV = wid >> 2;               // 0 = K cols, 1 = V cols
    uint32_t nchunk = (uint32_t)(isV << 3);

    int li = lane >> 3, lr = lane & 7;
    int roff = ((li & 1) << 3) + lr;  // for B ldmatrix addressing
    int ci   = li >> 1;
    int rm   = roff & 7;
    int g = lane >> 2, t = lane & 3;
    uint32_t w_base = sb + WH_OFF;

    float tm[2], tsum[2];
    tm[1] = -INFINITY; tsum[1] = 0.f;

    for (int tl = 0; tl < ntiles; ++tl) {
        int tbase = start + tl * TILE_M;
        int rbase = tbase + kw * 32 + g;    // lane's rows: rbase, +8, +16, +24
        const float* tp[4];
        const float* sp[4];
#pragma unroll
        for (int i = 0; i < 4; ++i) {
            size_t r = (size_t)b * L_ + rbase + i * 8;
            tp[i] = ts + r * DTS;
            sp[i] = seq + r * DSEQ;
        }
        int t2 = 2 * t;

        float acc[2][8][4];
#pragma unroll
        for (int ms = 0; ms < 2; ++ms)
#pragma unroll
            for (int n = 0; n < 8; ++n)
#pragma unroll
                for (int i = 0; i < 4; ++i) acc[ms][n][i] = 0.f;

        // A prefetch pipeline (depth 1). curA[ms] = {a0,a1,a2,a3}
        uint32_t curA[2][4], nxtA[2][4];
        // ks = 0: cols 2t (ts), 2t+8 (seq[2t])
#pragma unroll
        for (int ms = 0; ms < 2; ++ms) {
            curA[ms][0] = pack2(tp[2 * ms] + t2);
            curA[ms][1] = pack2(tp[2 * ms + 1] + t2);
            curA[ms][2] = pack2(sp[2 * ms] + t2);
            curA[ms][3] = pack2(sp[2 * ms + 1] + t2);
        }

#pragma unroll
        for (int ks = 0; ks < 8; ++ks) {
            if (ks < 7) {
                int off = 16 * (ks + 1) - 8 + t2;   // seq-relative col
#pragma unroll
                for (int ms = 0; ms < 2; ++ms) {
                    nxtA[ms][0] = pack2(sp[2 * ms] + off);
                    nxtA[ms][1] = pack2(sp[2 * ms + 1] + off);
                    nxtA[ms][2] = pack2(sp[2 * ms] + off + 8);
                    nxtA[ms][3] = pack2(sp[2 * ms + 1] + off + 8);
                }
            }
            uint32_t wh_row = w_base + (uint32_t)((ks * 16 + roff) * 256);
#pragma unroll
            for (int ntp = 0; ntp < 4; ++ntp) {
                uint32_t boff = (uint32_t)(((nchunk + 2 * ntp + ci) ^ rm) << 4);
                uint32_t b0, b1, b2, b3;
                LDSM_X4_T(b0, b1, b2, b3, wh_row + boff);
                mma_f16(acc[0][2 * ntp],     curA[0][0], curA[0][1], curA[0][2], curA[0][3], b0, b1);
                mma_f16(acc[0][2 * ntp + 1], curA[0][0], curA[0][1], curA[0][2], curA[0][3], b2, b3);
                mma_f16(acc[1][2 * ntp],     curA[1][0], curA[1][1], curA[1][2], curA[1][3], b0, b1);
                mma_f16(acc[1][2 * ntp + 1], curA[1][0], curA[1][1], curA[1][2], curA[1][3], b2, b3);
            }
#pragma unroll
            for (int ms = 0; ms < 2; ++ms)
#pragma unroll
                for (int i = 0; i < 4; ++i) curA[ms][i] = nxtA[ms][i];
        }

        // ---- K warps: scores ----
        if (!isV) {
#pragma unroll
            for (int ms = 0; ms < 2; ++ms) {
                float s0 = 0.f, s1 = 0.f;
#pragma unroll
                for (int nt = 0; nt < 8; ++nt) {
                    int c0 = 8 * nt + t2, c1 = c0 + 1;
                    float q0 = sQ[c0], q1 = sQ[c1];
                    float b0 = sBias[c0], b1 = sBias[c1];
                    s0 += q0 * rrelu(acc[ms][nt][0] + b0) + q1 * rrelu(acc[ms][nt][1] + b1);
                    s1 += q0 * rrelu(acc[ms][nt][2] + b0) + q1 * rrelu(acc[ms][nt][3] + b1);
                }
                s0 += __shfl_xor_sync(0xffffffffu, s0, 1);
                s0 += __shfl_xor_sync(0xffffffffu, s0, 2);
                s1 += __shfl_xor_sync(0xffffffffu, s1, 1);
                s1 += __shfl_xor_sync(0xffffffffu, s1, 2);
                if (t == 0) {
                    int r0 = kw * 32 + ms * 16 + g, r1 = r0 + 8;
                    sScore[r0] = (tbase + r0 < len) ? s0 : -INFINITY;
                    sScore[r1] = (tbase + r1 < len) ? s1 : -INFINITY;
                }
            }
        }
        __syncthreads();

        // ---- all-warp redundant softmax ----
        {
            float v0 = sScore[lane], v1 = sScore[lane + 32];
            float v2 = sScore[lane + 64], v3 = sScore[lane + 96];
            float mx = fmaxf(fmaxf(v0, v1), fmaxf(v2, v3));
#pragma unroll
            for (int o = 16; o >= 1; o >>= 1)
                mx = fmaxf(mx, __shfl_xor_sync(0xffffffffu, mx, o));
            float sum = __expf(v0 - mx) + __expf(v1 - mx)
                      + __expf(v2 - mx) + __expf(v3 - mx);
#pragma unroll
            for (int o = 16; o >= 1; o >>= 1)
                sum += __shfl_xor_sync(0xffffffffu, sum, o);
            tm[tl] = mx; tsum[tl] = sum;
        }

        // ---- V warps: weighted accumulate ----
        if (isV) {
            float mx = tm[tl];
            int rb = kw * 32;
            float wa = __expf(sScore[rb + g]      - mx);
            float wb = __expf(sScore[rb + g + 8]  - mx);
            float wc = __expf(sScore[rb + g + 16] - mx);
            float wd = __expf(sScore[rb + g + 24] - mx);
            float* sRed = tl ? sRed1 : sRed0;
#pragma unroll
            for (int nt = 0; nt < 8; ++nt) {
                int c0 = 8 * nt + t2, c1 = c0 + 1;
                float b0 = sBias[64 + c0], b1 = sBias[64 + c1];
                float p0 = wa * rrelu(acc[0][nt][0] + b0) + wb * rrelu(acc[0][nt][2] + b0)
                         + wc * rrelu(acc[1][nt][0] + b0) + wd * rrelu(acc[1][nt][2] + b0);
                float p1 = wa * rrelu(acc[0][nt][1] + b1) + wb * rrelu(acc[0][nt][3] + b1)
                         + wc * rrelu(acc[1][nt][1] + b1) + wd * rrelu(acc[1][nt][3] + b1);
                p0 += __shfl_xor_sync(0xffffffffu, p0, 4);
                p0 += __shfl_xor_sync(0xffffffffu, p0, 8);
                p0 += __shfl_xor_sync(0xffffffffu, p0, 16);
                p1 += __shfl_xor_sync(0xffffffffu, p1, 4);
                p1 += __shfl_xor_sync(0xffffffffu, p1, 8);
                p1 += __shfl_xor_sync(0xffffffffu, p1, 16);
                if (g == 0) {
                    sRed[kw * 64 + c0] = p0;
                    sRed[kw * 64 + c1] = p1;
                }
            }
        }
        __syncthreads();
    }

    // ---- in-block two-tile logsumexp merge ----
    float M = fmaxf(tm[0], tm[1]);
    float e0 = __expf(tm[0] - M);
    float e1 = __expf(tm[1] - M);
    if (tid < H_) {
        float A = (sRed0[tid] + sRed0[64 + tid] + sRed0[128 + tid] + sRed0[192 + tid]) * e0;
        if (ntiles == 2)
            A += (sRed1[tid] + sRed1[64 + tid] + sRed1[128 + tid] + sRed1[192 + tid]) * e1;
        g_acc[idx * H_ + tid] = A;
    }
    if (tid == 0) {
        g_m[idx] = M;
        g_s[idx] = tsum[0] * e0 + tsum[1] * e1;
    }

    // ---- last-block combine (threadfence reduction) ----
    __threadfence();
    __syncthreads();
    if (tid == 0) {
        int old = atomicAdd(&g_cnt[b], 1);
        *sLast = (old == nlive - 1);
    }
    __syncthreads();
    if (*sLast) {
        if (tid < H_) {
            volatile float* vm = g_m + b * NSPLIT;
            volatile float* vs = g_s + b * NSPLIT;
            volatile float* va = g_acc + (size_t)b * NSPLIT * H_;
            float MM = -INFINITY;
            for (int i = 0; i < nlive; ++i) MM = fmaxf(MM, vm[i]);
            float S = 0.f, A = 0.f;
            for (int i = 0; i < nlive; ++i) {
                float e = __expf(vm[i] - MM);
                S += vs[i] * e;
                A += va[i * H_ + tid] * e;
            }
            out[b * H_ + tid] = A / S;
        }
        if (tid == 0) g_cnt[b] = 0;   // reset for next replay
    }
}

// ---------------------------------------------------------------------------
extern "C" void kernel_launch(void* const* d_in, const int* in_sizes, int n_in,
                              void* d_out, int out_size) {
    const float* ts      = (const float*)d_in[0];
    const float* seq     = (const float*)d_in[1];
    const int*   lengths = (const int*)  d_in[2];
    const float* Wk      = (const float*)d_in[3];
    const float* bk      = (const float*)d_in[4];
    const float* Wq      = (const float*)d_in[5];
    const float* bq      = (const float*)d_in[6];
    const float* Wv      = (const float*)d_in[7];
    const float* bv      = (const float*)d_in[8];
    float* out = (float*)d_out;

    static int configured = 0;
    if (!configured) {
        cudaFuncSetAttribute(fused_attn,
                             cudaFuncAttributeMaxDynamicSharedMemorySize, SMEM_TOTAL);
        configured = 1;
    }

    dim3 grid(NSPLIT, B_);
    fused_attn<<<grid, TPB, SMEM_TOTAL>>>(ts, seq, lengths, Wk, bk, Wq, bq, Wv, bv, out);
}

// round 11
// speedup vs baseline: 1.0759x; 1.0736x over previous
#include <cuda_runtime.h>
#include <cuda_fp16.h>
#include <cstdint>
#include <math.h>

#define B_      64
#define L_      2048
#define DTS     8
#define DSEQ    120
#define DIN     128
#define H_      64
#define NSPLIT  8
#define TILE_B  256              // tokens per block
#define TILE_M  128              // tokens per MMA tile
#define TPB     256
#define SLOPE   0.2291666666666667f

// smem layout (bytes): header 5KB, X0 (32KB), X1 (32KB)
#define HDR     5120
#define X0_OFF  5120
#define X1_OFF  37888
#define SMEM_TOTAL 70656         // 2 blocks/SM

__device__ float g_m[B_ * NSPLIT];
__device__ float g_s[B_ * NSPLIT];
__device__ float g_acc[B_ * NSPLIT * H_];
__device__ float g_qlast[B_ * H_];
__device__ int   g_cnt[B_];      // zero-init; self-resetting per replay
// B-fragment table: [ks 0..7][grp 0..7][lane 0..31] -> uint4 (32 KB)
__device__ uint4 g_Bfrag[8 * 8 * 32];

__device__ __forceinline__ uint32_t smem_u32(const void* p) {
    uint32_t a;
    asm("{ .reg .u64 t; cvta.to.shared.u64 t, %1; cvt.u32.u64 %0, t; }" : "=r"(a) : "l"(p));
    return a;
}
__device__ __forceinline__ float rrelu(float x) { return x >= 0.f ? x : x * SLOPE; }
__device__ __forceinline__ uint32_t cvt_h2(float f0, float f1) {
    __half2 hh = __floats2half2_rn(f0, f1);
    return *reinterpret_cast<uint32_t*>(&hh);
}

#define LDSM_X4(r0, r1, r2, r3, addr) \
    asm volatile("ldmatrix.sync.aligned.m8n8.x4.shared.b16 {%0,%1,%2,%3}, [%4];" \
        : "=r"(r0), "=r"(r1), "=r"(r2), "=r"(r3) : "r"(addr))

__device__ __forceinline__ void mma_f16(float (&c)[4], uint32_t a0, uint32_t a1,
                                        uint32_t a2, uint32_t a3,
                                        uint32_t b0, uint32_t b1) {
    asm volatile(
        "mma.sync.aligned.m16n8k16.row.col.f32.f16.f16.f32 "
        "{%0,%1,%2,%3}, {%4,%5,%6,%7}, {%8,%9}, {%0,%1,%2,%3};"
        : "+f"(c[0]), "+f"(c[1]), "+f"(c[2]), "+f"(c[3])
        : "r"(a0), "r"(a1), "r"(a2), "r"(a3), "r"(b0), "r"(b1));
}

// ---------------------------------------------------------------------------
// prep: blocks 0-7 build the B-fragment table; blocks 8-71 compute q_last[b].
// ---------------------------------------------------------------------------
__global__ void __launch_bounds__(TPB, 2)
prep_kernel(const float* __restrict__ ts, const float* __restrict__ seq,
            const int* __restrict__ lengths,
            const float* __restrict__ Wk, const float* __restrict__ Wv,
            const float* __restrict__ Wq, const float* __restrict__ bq) {
    int tid = threadIdx.x;
    if (blockIdx.x < 8) {
        // ---- B-fragment table ----
        int wid = tid >> 5, lane = tid & 31;
        int wg = blockIdx.x * 8 + wid;        // 0..63
        int ks = wg >> 3, grp = wg & 7;
        int t = lane & 3, g = lane >> 2;
        int k0 = ks * 16 + 2 * t;
        int c = grp * 16 + g;
        // W(d, col): col<64 -> Wk, else Wv
        const float* W0 = (c < H_) ? (Wk + c) : (Wv + c - H_);
        const float* W1 = (c + 8 < H_) ? (Wk + c + 8) : (Wv + c + 8 - H_);
        uint4 f;
        f.x = cvt_h2(W0[k0 * H_],       W0[(k0 + 1) * H_]);
        f.y = cvt_h2(W0[(k0 + 8) * H_], W0[(k0 + 9) * H_]);
        f.z = cvt_h2(W1[k0 * H_],       W1[(k0 + 1) * H_]);
        f.w = cvt_h2(W1[(k0 + 8) * H_], W1[(k0 + 9) * H_]);
        g_Bfrag[wg * 32 + lane] = f;
    } else {
        // ---- q_last for batch b ----
        int b = blockIdx.x - 8;
        __shared__ float sXlast[DIN];
        __shared__ float sQpart[256];
        int len = lengths[b];
        if (tid < DIN) {
            int l = len - 1;
            sXlast[tid] = (tid < DTS) ? ts[((size_t)b * L_ + l) * DTS + tid]
                                      : seq[((size_t)b * L_ + l) * DSEQ + (tid - DTS)];
        }
        __syncthreads();
        {
            int h = tid & 63, part = tid >> 6;
            float s = 0.f;
            const float* wq = Wq + part * 32 * H_ + h;
#pragma unroll 8
            for (int d = 0; d < 32; ++d) s += sXlast[part * 32 + d] * wq[d * H_];
            sQpart[part * 64 + h] = s;
        }
        __syncthreads();
        if (tid < H_) {
            float s = sQpart[tid] + sQpart[64 + tid] + sQpart[128 + tid] + sQpart[192 + tid];
            g_qlast[b * H_ + tid] = rrelu(s + bq[tid]);
        }
    }
}

// ---------------------------------------------------------------------------
// fused: per (split, batch) block — 256-token span, two 128-row MMA tiles.
// Warps 0-3: K cols; warps 4-7: V cols; each warp 32 rows.
// B operands from precomputed global fragment table (L1-broadcast LDG.128).
// ---------------------------------------------------------------------------
__global__ void __launch_bounds__(TPB, 2)
fused_attn(const float* __restrict__ ts, const float* __restrict__ seq,
           const int* __restrict__ lengths,
           const float* __restrict__ bk, const float* __restrict__ bv,
           float* __restrict__ out) {
    int b   = blockIdx.y;
    int sp  = blockIdx.x;
    int len = lengths[b];
    int start = sp * TILE_B;
    int tid = threadIdx.x;
    int wid = tid >> 5, lane = tid & 31;
    int idx = b * NSPLIT + sp;
    int nlive = min(NSPLIT, (len + TILE_B - 1) / TILE_B);

    if (sp >= nlive) return;   // dead split
    int ntiles = min(2, (len - start + TILE_M - 1) >> 7);

    extern __shared__ char smem[];
    uint32_t sb = smem_u32(smem);
    float* sQ      = (float*)smem;             // 64
    float* sBias   = (float*)(smem + 256);     // 128
    float* sScore  = (float*)(smem + 768);     // 128
    float* sRed0   = (float*)(smem + 1280);    // 256
    float* sRed1   = (float*)(smem + 2304);    // 256
    int*   sLast   = (int*)(smem + 3328);

    // ---- header loads: bias + q ----
    if (tid < DIN) sBias[tid] = (tid < H_) ? bk[tid] : bv[tid - H_];
    if (tid < H_)  sQ[tid] = g_qlast[b * H_ + tid];

    // ---- X tiles (front-batched): fp32 -> fp16, swizzled ----
    for (int tl = 0; tl < ntiles; ++tl) {
        int xoff = X0_OFF + tl * 32768;
        int tbase = start + tl * TILE_M;
#pragma unroll
        for (int it = 0; it < 8; ++it) {
            int j = tid + it * TPB;           // 0..2047
            int row = j >> 4, ch = j & 15;
            int token = tbase + row;
            const float* src = (ch == 0)
                ? (ts + ((size_t)b * L_ + token) * DTS)
                : (seq + ((size_t)b * L_ + token) * DSEQ + (ch * 8 - 8));
            float4 f0 = ((const float4*)src)[0];
            float4 f1 = ((const float4*)src)[1];
            uint4 v = make_uint4(cvt_h2(f0.x, f0.y), cvt_h2(f0.z, f0.w),
                                 cvt_h2(f1.x, f1.y), cvt_h2(f1.z, f1.w));
            uint32_t off = (uint32_t)(row * 256 + ((ch ^ (row & 7)) << 4));
            *(uint4*)(smem + xoff + off) = v;
        }
    }
    __syncthreads();

    int kw = wid & 3;                 // row group
    int isV = wid >> 2;               // 0 = K cols (0-63), 1 = V cols (64-127)

    int li = lane >> 3, lr = lane & 7;
    int roff = ((li & 1) << 3) + lr;
    int ci   = li >> 1;
    int rm   = roff & 7;
    int g = lane >> 2, t = lane & 3;
    int t2 = 2 * t;

    // B-frag stream for this warp: grp base = isV*4
    const uint4* bf = g_Bfrag + (isV * 4) * 32 + lane;

    float tm[2], tsum[2];
    tm[1] = -INFINITY; tsum[1] = 0.f;

    for (int tl = 0; tl < ntiles; ++tl) {
        int tbase = start + tl * TILE_M;
        uint32_t a_row0 = sb + X0_OFF + (uint32_t)(tl * 32768)
                        + (uint32_t)((kw * 32 + roff) * 256);
        uint32_t a_row1 = a_row0 + 16 * 256;

        float acc[2][8][4];
#pragma unroll
        for (int ms = 0; ms < 2; ++ms)
#pragma unroll
            for (int n = 0; n < 8; ++n)
#pragma unroll
                for (int i = 0; i < 4; ++i) acc[ms][n][i] = 0.f;

#pragma unroll
        for (int ks = 0; ks < 8; ++ks) {
            uint32_t aoff = ((uint32_t)((2 * ks + ci) ^ rm)) << 4;
            uint32_t a00, a01, a02, a03, a10, a11, a12, a13;
            LDSM_X4(a00, a01, a02, a03, a_row0 + aoff);
            LDSM_X4(a10, a11, a12, a13, a_row1 + aoff);
#pragma unroll
            for (int ntp = 0; ntp < 4; ++ntp) {
                uint4 f = bf[(ks * 8 + ntp) * 32];
                mma_f16(acc[0][2 * ntp],     a00, a01, a02, a03, f.x, f.y);
                mma_f16(acc[0][2 * ntp + 1], a00, a01, a02, a03, f.z, f.w);
                mma_f16(acc[1][2 * ntp],     a10, a11, a12, a13, f.x, f.y);
                mma_f16(acc[1][2 * ntp + 1], a10, a11, a12, a13, f.z, f.w);
            }
        }

        // ---- K warps: scores ----
        if (!isV) {
#pragma unroll
            for (int ms = 0; ms < 2; ++ms) {
                float s0 = 0.f, s1 = 0.f;
#pragma unroll
                for (int nt = 0; nt < 8; ++nt) {
                    int c0 = 8 * nt + t2, c1 = c0 + 1;
                    float q0 = sQ[c0], q1 = sQ[c1];
                    float b0 = sBias[c0], b1 = sBias[c1];
                    s0 += q0 * rrelu(acc[ms][nt][0] + b0) + q1 * rrelu(acc[ms][nt][1] + b1);
                    s1 += q0 * rrelu(acc[ms][nt][2] + b0) + q1 * rrelu(acc[ms][nt][3] + b1);
                }
                s0 += __shfl_xor_sync(0xffffffffu, s0, 1);
                s0 += __shfl_xor_sync(0xffffffffu, s0, 2);
                s1 += __shfl_xor_sync(0xffffffffu, s1, 1);
                s1 += __shfl_xor_sync(0xffffffffu, s1, 2);
                if (t == 0) {
                    int r0 = kw * 32 + ms * 16 + g, r1 = r0 + 8;
                    sScore[r0] = (tbase + r0 < len) ? s0 : -INFINITY;
                    sScore[r1] = (tbase + r1 < len) ? s1 : -INFINITY;
                }
            }
        }
        __syncthreads();

        // ---- all-warp redundant softmax ----
        {
            float v0 = sScore[lane], v1 = sScore[lane + 32];
            float v2 = sScore[lane + 64], v3 = sScore[lane + 96];
            float mx = fmaxf(fmaxf(v0, v1), fmaxf(v2, v3));
#pragma unroll
            for (int o = 16; o >= 1; o >>= 1)
                mx = fmaxf(mx, __shfl_xor_sync(0xffffffffu, mx, o));
            float sum = __expf(v0 - mx) + __expf(v1 - mx)
                      + __expf(v2 - mx) + __expf(v3 - mx);
#pragma unroll
            for (int o = 16; o >= 1; o >>= 1)
                sum += __shfl_xor_sync(0xffffffffu, sum, o);
            tm[tl] = mx; tsum[tl] = sum;
        }

        // ---- V warps: weighted accumulate ----
        if (isV) {
            float mx = tm[tl];
            int rb = kw * 32;
            float wa = __expf(sScore[rb + g]      - mx);
            float wb = __expf(sScore[rb + g + 8]  - mx);
            float wc = __expf(sScore[rb + g + 16] - mx);
            float wd = __expf(sScore[rb + g + 24] - mx);
            float* sRed = tl ? sRed1 : sRed0;
#pragma unroll
            for (int nt = 0; nt < 8; ++nt) {
                int c0 = 8 * nt + t2, c1 = c0 + 1;
                float b0 = sBias[64 + c0], b1 = sBias[64 + c1];
                float p0 = wa * rrelu(acc[0][nt][0] + b0) + wb * rrelu(acc[0][nt][2] + b0)
                         + wc * rrelu(acc[1][nt][0] + b0) + wd * rrelu(acc[1][nt][2] + b0);
                float p1 = wa * rrelu(acc[0][nt][1] + b1) + wb * rrelu(acc[0][nt][3] + b1)
                         + wc * rrelu(acc[1][nt][1] + b1) + wd * rrelu(acc[1][nt][3] + b1);
                p0 += __shfl_xor_sync(0xffffffffu, p0, 4);
                p0 += __shfl_xor_sync(0xffffffffu, p0, 8);
                p0 += __shfl_xor_sync(0xffffffffu, p0, 16);
                p1 += __shfl_xor_sync(0xffffffffu, p1, 4);
                p1 += __shfl_xor_sync(0xffffffffu, p1, 8);
                p1 += __shfl_xor_sync(0xffffffffu, p1, 16);
                if (g == 0) {
                    sRed[kw * 64 + c0] = p0;
                    sRed[kw * 64 + c1] = p1;
                }
            }
        }
        __syncthreads();
    }

    // ---- in-block two-tile logsumexp merge ----
    float M = fmaxf(tm[0], tm[1]);
    float e0 = __expf(tm[0] - M);
    float e1 = __expf(tm[1] - M);
    if (tid < H_) {
        float A = (sRed0[tid] + sRed0[64 + tid] + sRed0[128 + tid] + sRed0[192 + tid]) * e0;
        if (ntiles == 2)
            A += (sRed1[tid] + sRed1[64 + tid] + sRed1[128 + tid] + sRed1[192 + tid]) * e1;
        g_acc[idx * H_ + tid] = A;
    }
    if (tid == 0) {
        g_m[idx] = M;
        g_s[idx] = tsum[0] * e0 + tsum[1] * e1;
    }

    // ---- last-block combine (threadfence reduction) ----
    __threadfence();
    __syncthreads();
    if (tid == 0) {
        int old = atomicAdd(&g_cnt[b], 1);
        *sLast = (old == nlive - 1);
    }
    __syncthreads();
    if (*sLast) {
        if (tid < H_) {
            volatile float* vm = g_m + b * NSPLIT;
            volatile float* vs = g_s + b * NSPLIT;
            volatile float* va = g_acc + (size_t)b * NSPLIT * H_;
            float MM = -INFINITY;
            for (int i = 0; i < nlive; ++i) MM = fmaxf(MM, vm[i]);
            float S = 0.f, A = 0.f;
            for (int i = 0; i < nlive; ++i) {
                float e = __expf(vm[i] - MM);
                S += vs[i] * e;
                A += va[i * H_ + tid] * e;
            }
            out[b * H_ + tid] = A / S;
        }
        if (tid == 0) g_cnt[b] = 0;   // reset for next replay
    }
}

// ---------------------------------------------------------------------------
extern "C" void kernel_launch(void* const* d_in, const int* in_sizes, int n_in,
                              void* d_out, int out_size) {
    const float* ts      = (const float*)d_in[0];
    const float* seq     = (const float*)d_in[1];
    const int*   lengths = (const int*)  d_in[2];
    const float* Wk      = (const float*)d_in[3];
    const float* bk      = (const float*)d_in[4];
    const float* Wq      = (const float*)d_in[5];
    const float* bq      = (const float*)d_in[6];
    const float* Wv      = (const float*)d_in[7];
    const float* bv      = (const float*)d_in[8];
    float* out = (float*)d_out;

    static int configured = 0;
    if (!configured) {
        cudaFuncSetAttribute(fused_attn,
                             cudaFuncAttributeMaxDynamicSharedMemorySize, SMEM_TOTAL);
        configured = 1;
    }

    prep_kernel<<<8 + B_, TPB>>>(ts, seq, lengths, Wk, Wv, Wq, bq);
    dim3 grid(NSPLIT, B_);
    fused_attn<<<grid, TPB, SMEM_TOTAL>>>(ts, seq, lengths, bk, bv, out);
}

// round 12
// speedup vs baseline: 1.0874x; 1.0106x over previous
#include <cuda_runtime.h>
#include <cuda_fp16.h>
#include <cstdint>
#include <math.h>

#define B_      64
#define L_      2048
#define DTS     8
#define DSEQ    120
#define DIN     128
#define H_      64
#define NSPLIT  16
#define TILE_M  128              // tokens per block
#define TPB     256
#define SLOPE   0.2291666666666667f

// smem layout (bytes): header 5KB, X (32KB)
#define HDR     5120
#define X0_OFF  5120
#define SMEM_TOTAL 37888         // 2+ blocks/SM (reg-limited to 2)

__device__ float g_m[B_ * NSPLIT];
__device__ float g_s[B_ * NSPLIT];
__device__ float g_acc[B_ * NSPLIT * H_];
__device__ float g_qlast[B_ * H_];
__device__ int   g_cnt[B_];      // zero-init; self-resetting per replay
// B-fragment table: [ks 0..7][grp 0..7][lane 0..31] -> uint4 (32 KB)
__device__ uint4 g_Bfrag[8 * 8 * 32];

__device__ __forceinline__ uint32_t smem_u32(const void* p) {
    uint32_t a;
    asm("{ .reg .u64 t; cvta.to.shared.u64 t, %1; cvt.u32.u64 %0, t; }" : "=r"(a) : "l"(p));
    return a;
}
__device__ __forceinline__ float rrelu(float x) { return x >= 0.f ? x : x * SLOPE; }
__device__ __forceinline__ uint32_t cvt_h2(float f0, float f1) {
    __half2 hh = __floats2half2_rn(f0, f1);
    return *reinterpret_cast<uint32_t*>(&hh);
}

#define LDSM_X4(r0, r1, r2, r3, addr) \
    asm volatile("ldmatrix.sync.aligned.m8n8.x4.shared.b16 {%0,%1,%2,%3}, [%4];" \
        : "=r"(r0), "=r"(r1), "=r"(r2), "=r"(r3) : "r"(addr))

__device__ __forceinline__ void mma_f16(float (&c)[4], uint32_t a0, uint32_t a1,
                                        uint32_t a2, uint32_t a3,
                                        uint32_t b0, uint32_t b1) {
    asm volatile(
        "mma.sync.aligned.m16n8k16.row.col.f32.f16.f16.f32 "
        "{%0,%1,%2,%3}, {%4,%5,%6,%7}, {%8,%9}, {%0,%1,%2,%3};"
        : "+f"(c[0]), "+f"(c[1]), "+f"(c[2]), "+f"(c[3])
        : "r"(a0), "r"(a1), "r"(a2), "r"(a3), "r"(b0), "r"(b1));
}

// ---------------------------------------------------------------------------
// prep: blocks 0-7 build the B-fragment table; blocks 8-71 compute q_last[b].
// ---------------------------------------------------------------------------
__global__ void __launch_bounds__(TPB, 2)
prep_kernel(const float* __restrict__ ts, const float* __restrict__ seq,
            const int* __restrict__ lengths,
            const float* __restrict__ Wk, const float* __restrict__ Wv,
            const float* __restrict__ Wq, const float* __restrict__ bq) {
    int tid = threadIdx.x;
    if (blockIdx.x < 8) {
        int wid = tid >> 5, lane = tid & 31;
        int wg = blockIdx.x * 8 + wid;        // 0..63
        int ks = wg >> 3, grp = wg & 7;
        int t = lane & 3, g = lane >> 2;
        int k0 = ks * 16 + 2 * t;
        int c = grp * 16 + g;
        const float* W0 = (c < H_) ? (Wk + c) : (Wv + c - H_);
        const float* W1 = (c + 8 < H_) ? (Wk + c + 8) : (Wv + c + 8 - H_);
        uint4 f;
        f.x = cvt_h2(W0[k0 * H_],       W0[(k0 + 1) * H_]);
        f.y = cvt_h2(W0[(k0 + 8) * H_], W0[(k0 + 9) * H_]);
        f.z = cvt_h2(W1[k0 * H_],       W1[(k0 + 1) * H_]);
        f.w = cvt_h2(W1[(k0 + 8) * H_], W1[(k0 + 9) * H_]);
        g_Bfrag[wg * 32 + lane] = f;
    } else {
        int b = blockIdx.x - 8;
        __shared__ float sXlast[DIN];
        __shared__ float sQpart[256];
        int len = lengths[b];
        if (tid < DIN) {
            int l = len - 1;
            sXlast[tid] = (tid < DTS) ? ts[((size_t)b * L_ + l) * DTS + tid]
                                      : seq[((size_t)b * L_ + l) * DSEQ + (tid - DTS)];
        }
        __syncthreads();
        {
            int h = tid & 63, part = tid >> 6;
            float s = 0.f;
            const float* wq = Wq + part * 32 * H_ + h;
#pragma unroll 8
            for (int d = 0; d < 32; ++d) s += sXlast[part * 32 + d] * wq[d * H_];
            sQpart[part * 64 + h] = s;
        }
        __syncthreads();
        if (tid < H_) {
            float s = sQpart[tid] + sQpart[64 + tid] + sQpart[128 + tid] + sQpart[192 + tid];
            g_qlast[b * H_ + tid] = rrelu(s + bq[tid]);
        }
    }
}

// ---------------------------------------------------------------------------
// fused: per (split, batch) block — ONE 128-token tile.
// Warps 0-3: K cols; warps 4-7: V cols; each warp 32 rows.
// B operands from precomputed global fragment table (L1-broadcast LDG.128).
// ---------------------------------------------------------------------------
__global__ void __launch_bounds__(TPB, 2)
fused_attn(const float* __restrict__ ts, const float* __restrict__ seq,
           const int* __restrict__ lengths,
           const float* __restrict__ bk, const float* __restrict__ bv,
           float* __restrict__ out) {
    int b   = blockIdx.y;
    int sp  = blockIdx.x;
    int len = lengths[b];
    int start = sp * TILE_M;
    int tid = threadIdx.x;
    int wid = tid >> 5, lane = tid & 31;
    int idx = b * NSPLIT + sp;
    int nlive = min(NSPLIT, (len + TILE_M - 1) >> 7);

    if (sp >= nlive) return;   // dead split

    extern __shared__ char smem[];
    uint32_t sb = smem_u32(smem);
    float* sQ      = (float*)smem;             // 64
    float* sBias   = (float*)(smem + 256);     // 128
    float* sScore  = (float*)(smem + 768);     // 128
    float* sRed    = (float*)(smem + 1280);    // 256
    int*   sLast   = (int*)(smem + 2304);

    // ---- header loads: bias + q ----
    if (tid < DIN) sBias[tid] = (tid < H_) ? bk[tid] : bv[tid - H_];
    if (tid < H_)  sQ[tid] = g_qlast[b * H_ + tid];

    // ---- X tile: fp32 -> fp16, swizzled ----
#pragma unroll
    for (int it = 0; it < 8; ++it) {
        int j = tid + it * TPB;               // 0..2047
        int row = j >> 4, ch = j & 15;
        int token = start + row;
        const float* src = (ch == 0)
            ? (ts + ((size_t)b * L_ + token) * DTS)
            : (seq + ((size_t)b * L_ + token) * DSEQ + (ch * 8 - 8));
        float4 f0 = ((const float4*)src)[0];
        float4 f1 = ((const float4*)src)[1];
        uint4 v = make_uint4(cvt_h2(f0.x, f0.y), cvt_h2(f0.z, f0.w),
                             cvt_h2(f1.x, f1.y), cvt_h2(f1.z, f1.w));
        uint32_t off = (uint32_t)(row * 256 + ((ch ^ (row & 7)) << 4));
        *(uint4*)(smem + X0_OFF + off) = v;
    }
    __syncthreads();

    int kw = wid & 3;                 // row group
    int isV = wid >> 2;               // 0 = K cols (0-63), 1 = V cols (64-127)

    int li = lane >> 3, lr = lane & 7;
    int roff = ((li & 1) << 3) + lr;
    int ci   = li >> 1;
    int rm   = roff & 7;
    int g = lane >> 2, t = lane & 3;
    int t2 = 2 * t;

    const uint4* bf = g_Bfrag + (isV * 4) * 32 + lane;

    uint32_t a_row0 = sb + X0_OFF + (uint32_t)((kw * 32 + roff) * 256);
    uint32_t a_row1 = a_row0 + 16 * 256;

    float acc[2][8][4];
#pragma unroll
    for (int ms = 0; ms < 2; ++ms)
#pragma unroll
        for (int n = 0; n < 8; ++n)
#pragma unroll
            for (int i = 0; i < 4; ++i) acc[ms][n][i] = 0.f;

#pragma unroll
    for (int ks = 0; ks < 8; ++ks) {
        uint32_t aoff = ((uint32_t)((2 * ks + ci) ^ rm)) << 4;
        uint32_t a00, a01, a02, a03, a10, a11, a12, a13;
        LDSM_X4(a00, a01, a02, a03, a_row0 + aoff);
        LDSM_X4(a10, a11, a12, a13, a_row1 + aoff);
#pragma unroll
        for (int ntp = 0; ntp < 4; ++ntp) {
            uint4 f = bf[(ks * 8 + ntp) * 32];
            mma_f16(acc[0][2 * ntp],     a00, a01, a02, a03, f.x, f.y);
            mma_f16(acc[0][2 * ntp + 1], a00, a01, a02, a03, f.z, f.w);
            mma_f16(acc[1][2 * ntp],     a10, a11, a12, a13, f.x, f.y);
            mma_f16(acc[1][2 * ntp + 1], a10, a11, a12, a13, f.z, f.w);
        }
    }

    // ---- K warps: scores ----
    if (!isV) {
#pragma unroll
        for (int ms = 0; ms < 2; ++ms) {
            float s0 = 0.f, s1 = 0.f;
#pragma unroll
            for (int nt = 0; nt < 8; ++nt) {
                int c0 = 8 * nt + t2, c1 = c0 + 1;
                float q0 = sQ[c0], q1 = sQ[c1];
                float b0 = sBias[c0], b1 = sBias[c1];
                s0 += q0 * rrelu(acc[ms][nt][0] + b0) + q1 * rrelu(acc[ms][nt][1] + b1);
                s1 += q0 * rrelu(acc[ms][nt][2] + b0) + q1 * rrelu(acc[ms][nt][3] + b1);
            }
            s0 += __shfl_xor_sync(0xffffffffu, s0, 1);
            s0 += __shfl_xor_sync(0xffffffffu, s0, 2);
            s1 += __shfl_xor_sync(0xffffffffu, s1, 1);
            s1 += __shfl_xor_sync(0xffffffffu, s1, 2);
            if (t == 0) {
                int r0 = kw * 32 + ms * 16 + g, r1 = r0 + 8;
                sScore[r0] = (start + r0 < len) ? s0 : -INFINITY;
                sScore[r1] = (start + r1 < len) ? s1 : -INFINITY;
            }
        }
    }
    __syncthreads();

    // ---- all-warp redundant softmax ----
    float mx, sum;
    {
        float v0 = sScore[lane], v1 = sScore[lane + 32];
        float v2 = sScore[lane + 64], v3 = sScore[lane + 96];
        mx = fmaxf(fmaxf(v0, v1), fmaxf(v2, v3));
#pragma unroll
        for (int o = 16; o >= 1; o >>= 1)
            mx = fmaxf(mx, __shfl_xor_sync(0xffffffffu, mx, o));
        sum = __expf(v0 - mx) + __expf(v1 - mx)
            + __expf(v2 - mx) + __expf(v3 - mx);
#pragma unroll
        for (int o = 16; o >= 1; o >>= 1)
            sum += __shfl_xor_sync(0xffffffffu, sum, o);
    }

    // ---- V warps: weighted accumulate ----
    if (isV) {
        int rb = kw * 32;
        float wa = __expf(sScore[rb + g]      - mx);
        float wb = __expf(sScore[rb + g + 8]  - mx);
        float wc = __expf(sScore[rb + g + 16] - mx);
        float wd = __expf(sScore[rb + g + 24] - mx);
#pragma unroll
        for (int nt = 0; nt < 8; ++nt) {
            int c0 = 8 * nt + t2, c1 = c0 + 1;
            float b0 = sBias[64 + c0], b1 = sBias[64 + c1];
            float p0 = wa * rrelu(acc[0][nt][0] + b0) + wb * rrelu(acc[0][nt][2] + b0)
                     + wc * rrelu(acc[1][nt][0] + b0) + wd * rrelu(acc[1][nt][2] + b0);
            float p1 = wa * rrelu(acc[0][nt][1] + b1) + wb * rrelu(acc[0][nt][3] + b1)
                     + wc * rrelu(acc[1][nt][1] + b1) + wd * rrelu(acc[1][nt][3] + b1);
            p0 += __shfl_xor_sync(0xffffffffu, p0, 4);
            p0 += __shfl_xor_sync(0xffffffffu, p0, 8);
            p0 += __shfl_xor_sync(0xffffffffu, p0, 16);
            p1 += __shfl_xor_sync(0xffffffffu, p1, 4);
            p1 += __shfl_xor_sync(0xffffffffu, p1, 8);
            p1 += __shfl_xor_sync(0xffffffffu, p1, 16);
            if (g == 0) {
                sRed[kw * 64 + c0] = p0;
                sRed[kw * 64 + c1] = p1;
            }
        }
    }
    __syncthreads();

    // ---- per-split partials ----
    if (tid < H_) {
        g_acc[idx * H_ + tid] = sRed[tid] + sRed[64 + tid]
                              + sRed[128 + tid] + sRed[192 + tid];
    }
    if (tid == 0) { g_m[idx] = mx; g_s[idx] = sum; }

    // ---- last-block combine (threadfence reduction) ----
    __threadfence();
    __syncthreads();
    if (tid == 0) {
        int old = atomicAdd(&g_cnt[b], 1);
        *sLast = (old == nlive - 1);
    }
    __syncthreads();
    if (*sLast) {
        if (tid < H_) {
            volatile float* vm = g_m + b * NSPLIT;
            volatile float* vs = g_s + b * NSPLIT;
            volatile float* va = g_acc + (size_t)b * NSPLIT * H_;
            float MM = -INFINITY;
            for (int i = 0; i < nlive; ++i) MM = fmaxf(MM, vm[i]);
            float S = 0.f, A = 0.f;
            for (int i = 0; i < nlive; ++i) {
                float e = __expf(vm[i] - MM);
                S += vs[i] * e;
                A += va[i * H_ + tid] * e;
            }
            out[b * H_ + tid] = A / S;
        }
        if (tid == 0) g_cnt[b] = 0;   // reset for next replay
    }
}

// ---------------------------------------------------------------------------
extern "C" void kernel_launch(void* const* d_in, const int* in_sizes, int n_in,
                              void* d_out, int out_size) {
    const float* ts      = (const float*)d_in[0];
    const float* seq     = (const float*)d_in[1];
    const int*   lengths = (const int*)  d_in[2];
    const float* Wk      = (const float*)d_in[3];
    const float* bk      = (const float*)d_in[4];
    const float* Wq      = (const float*)d_in[5];
    const float* bq      = (const float*)d_in[6];
    const float* Wv      = (const float*)d_in[7];
    const float* bv      = (const float*)d_in[8];
    float* out = (float*)d_out;

    static int configured = 0;
    if (!configured) {
        cudaFuncSetAttribute(fused_attn,
                             cudaFuncAttributeMaxDynamicSharedMemorySize, SMEM_TOTAL);
        configured = 1;
    }

    prep_kernel<<<8 + B_, TPB>>>(ts, seq, lengths, Wk, Wv, Wq, bq);
    dim3 grid(NSPLIT, B_);
    fused_attn<<<grid, TPB, SMEM_TOTAL>>>(ts, seq, lengths, bk, bv, out);
}